// round 5
// baseline (speedup 1.0000x reference)
#include <cuda_runtime.h>
#include <math.h>

#define HHv 83
#define WWv 25
#define AAv 9
#define N_ANCH (HHv*WWv*AAv)   /* 18675 */
#define BATCH 16
#define PRE 12000
#define POST 2000
#define MIN_SIZE 16.0f
#define NMS_T 0.7f
#define IMG_XF 1333.0f
#define IMG_YF 402.0f
#define FLIP_NEG_INF 0x007FFFFFu
#define CHUNK 64
#define NMS_THREADS 512

__device__ float4   g_boxes[BATCH * N_ANCH];
__device__ unsigned g_skey [BATCH * N_ANCH];
__device__ float4   g_candBox[BATCH * PRE];
__device__ int      g_candCount[BATCH];

__device__ __forceinline__ unsigned flipf(float f){
    unsigned u = __float_as_uint(f);
    return (u & 0x80000000u) ? ~u : (u | 0x80000000u);
}

// ---------------------------------------------------------------- K1: decode
__global__ void k_decode(const float4* __restrict__ anchors,
                         const float*  __restrict__ cls,
                         const float4* __restrict__ pred)
{
    int t = blockIdx.x*blockDim.x + threadIdx.x;
    if (t >= BATCH*N_ANCH) return;
    int b = t / N_ANCH, i = t - b*N_ANCH;

    float4 a = anchors[i];
    float ah  = __fsub_rn(a.w, a.y);
    float aw  = __fsub_rn(a.z, a.x);
    float acy = __fadd_rn(a.y, __fmul_rn(0.5f, ah));
    float acx = __fadd_rn(a.x, __fmul_rn(0.5f, aw));

    float4 p = pred[t];   // dx, dy, dw, dh
    float cy = __fadd_rn(__fmul_rn(p.y, ah), acy);
    float cx = __fadd_rn(__fmul_rn(p.x, aw), acx);
    float eh = (float)exp((double)p.w);
    float ew = (float)exp((double)p.z);
    float h  = __fmul_rn(eh, ah);
    float w  = __fmul_rn(ew, aw);

    float hw = __fmul_rn(0.5f, w);
    float hh = __fmul_rn(0.5f, h);
    float x1 = fminf(fmaxf(__fsub_rn(cx, hw), 0.f), IMG_XF);
    float y1 = fminf(fmaxf(__fsub_rn(cy, hh), 0.f), IMG_YF);
    float x2 = fminf(fmaxf(__fadd_rn(cx, hw), 0.f), IMG_XF);
    float y2 = fminf(fmaxf(__fadd_rn(cy, hh), 0.f), IMG_YF);

    g_boxes[t] = make_float4(x1, y1, x2, y2);

    bool valid = (__fsub_rn(y2, y1) >= MIN_SIZE) && (__fsub_rn(x2, x1) >= MIN_SIZE);
    float s = valid ? cls[b*(2*N_ANCH) + 2*i + 1] : -INFINITY;
    g_skey[t] = flipf(s);
}

// -------------------------------------------- K2: exact top-PRE select + compact
__global__ void __launch_bounds__(1024) k_select()
{
    int b = blockIdx.x;
    const unsigned* skey = g_skey + b*N_ANCH;
    const int BD = 1024;
    int tid = threadIdx.x;

    __shared__ int      hist[2048];
    __shared__ unsigned s_pfx, s_T;
    __shared__ int      s_r, s_cEq, s_binI, s_rr, s_eqN, s_Tidx;
    __shared__ int      s_eqIdx[32];

    for (int j=tid;j<2048;j+=BD) hist[j]=0;
    __syncthreads();
    for (int i=tid;i<N_ANCH;i+=BD) atomicAdd(&hist[skey[i]>>21], 1);
    __syncthreads();
    if (tid==0){
        int cum=0, r=PRE; unsigned b0=0;
        for (int bin=2047; bin>=0; --bin){
            int c=hist[bin];
            if (cum+c>=PRE){ b0=(unsigned)bin; r=PRE-cum; break; }
            cum+=c;
        }
        s_pfx=b0; s_r=r;
    }
    __syncthreads();
    unsigned b0 = s_pfx; int r = s_r;

    for (int j=tid;j<2048;j+=BD) hist[j]=0;
    __syncthreads();
    for (int i=tid;i<N_ANCH;i+=BD){
        unsigned k=skey[i];
        if ((k>>21)==b0) atomicAdd(&hist[(k>>10)&0x7FFu],1);
    }
    __syncthreads();
    if (tid==0){
        int cum=0; unsigned b1=0; int rr=r;
        for (int bin=2047;bin>=0;--bin){
            int c=hist[bin];
            if (cum+c>=r){ b1=(unsigned)bin; rr=r-cum; break; }
            cum+=c;
        }
        s_pfx = (b0<<11)|b1; s_r=rr;
    }
    __syncthreads();
    unsigned pfx = s_pfx; r = s_r;

    for (int j=tid;j<1024;j+=BD) hist[j]=0;
    __syncthreads();
    for (int i=tid;i<N_ANCH;i+=BD){
        unsigned k=skey[i];
        if ((k>>10)==pfx) atomicAdd(&hist[k&0x3FFu],1);
    }
    __syncthreads();
    if (tid==0){
        int cum=0; unsigned b2=0; int rr=r; int cEq=0;
        for (int bin=1023;bin>=0;--bin){
            int c=hist[bin];
            if (cum+c>=r){ b2=(unsigned)bin; rr=r-cum; cEq=c; break; }
            cum+=c;
        }
        s_T = (pfx<<10)|b2; s_r=rr; s_cEq=cEq;
    }
    __syncthreads();
    unsigned T = s_T; r = s_r; int cEq = s_cEq;

    int Tidx;
    if (r >= cEq){
        Tidx = N_ANCH;
    } else {
        for (int j=tid;j<2048;j+=BD) hist[j]=0;
        __syncthreads();
        for (int i=tid;i<N_ANCH;i+=BD)
            if (skey[i]==T) atomicAdd(&hist[i>>4],1);
        __syncthreads();
        if (tid==0){
            int cum=0, binI=0, rr=r;
            for (int bin=0;bin<2048;++bin){
                int c=hist[bin];
                if (cum+c>=r){ binI=bin; rr=r-cum; break; }
                cum+=c;
            }
            s_binI=binI; s_rr=rr; s_eqN=0;
        }
        __syncthreads();
        int binI=s_binI;
        for (int i=tid;i<N_ANCH;i+=BD)
            if (skey[i]==T && (i>>4)==binI){
                int p=atomicAdd(&s_eqN,1);
                s_eqIdx[p]=i;
            }
        __syncthreads();
        if (tid==0){
            int n=s_eqN, need=s_rr;
            for (int a2=0;a2<n;a2++)
                for (int b2=a2+1;b2<n;b2++)
                    if (s_eqIdx[b2]<s_eqIdx[a2]){
                        int tmp=s_eqIdx[a2]; s_eqIdx[a2]=s_eqIdx[b2]; s_eqIdx[b2]=tmp;
                    }
            s_Tidx = s_eqIdx[need-1];
        }
        __syncthreads();
        Tidx = s_Tidx;
    }

    __shared__ int s_wcnt[32], s_wbase[32], s_total;
    if (tid==0) s_total=0;
    __syncthreads();

    const float4* boxes = g_boxes   + b*N_ANCH;
    float4*       cand  = g_candBox + b*PRE;
    int lane = tid & 31, wid = tid>>5;
    int nCh = (N_ANCH + BD - 1)/BD;

    for (int c=0;c<nCh;c++){
        int pos = c*BD + tid;
        int i = N_ANCH-1-pos;
        bool pred=false;
        if (i>=0){
            unsigned k = skey[i];
            bool valid = (k != FLIP_NEG_INF);
            bool sel   = (k > T) || (k==T && i<=Tidx);
            pred = valid && sel;
        }
        unsigned bal = __ballot_sync(0xffffffffu, pred);
        if (lane==0) s_wcnt[wid]=__popc(bal);
        __syncthreads();
        if (tid==0){
            int acc=s_total;
            for (int w2=0;w2<32;w2++){ s_wbase[w2]=acc; acc+=s_wcnt[w2]; }
            s_total=acc;
        }
        __syncthreads();
        if (pred){
            int p = s_wbase[wid] + __popc(bal & ((1u<<lane)-1u));
            cand[p] = boxes[i];
        }
        __syncthreads();
    }
    if (tid==0) g_candCount[b]=s_total;
}

// ---------------------------------------------------------------- K3: greedy NMS
__device__ __forceinline__ bool iou_gt(const float4& A, float aA,
                                       const float4& Bx, float aB)
{
    float xx1=fmaxf(A.x,Bx.x), yy1=fmaxf(A.y,Bx.y);
    float xx2=fminf(A.z,Bx.z), yy2=fminf(A.w,Bx.w);
    float iw=__fadd_rn(__fsub_rn(xx2,xx1),1.f);
    float ih=__fadd_rn(__fsub_rn(yy2,yy1),1.f);
    float inter=__fmul_rn(fmaxf(iw,0.f), fmaxf(ih,0.f));
    float uni = __fsub_rn(__fadd_rn(aA,aB), inter);
    float ovr = __fdiv_rn(inter, uni);
    return ovr > NMS_T;
}

__device__ __forceinline__ float areaf(const float4& bx){
    return __fmul_rn(__fadd_rn(__fsub_rn(bx.z,bx.x),1.f),
                     __fadd_rn(__fsub_rn(bx.w,bx.y),1.f));
}

__global__ void __launch_bounds__(NMS_THREADS)
k_nms(float* __restrict__ outRois, float* __restrict__ outMask, int writeMask)
{
    __shared__ float4             kb[POST];
    __shared__ float              ka[POST];
    __shared__ float4             cbox[CHUNK];
    __shared__ float              carea[CHUNK];
    __shared__ unsigned long long s_mat[CHUNK];
    __shared__ unsigned           s_supw[16];
    __shared__ unsigned short     s_kidx[POST];
    __shared__ int                s_new[CHUNK];
    __shared__ float              s_part[2][6];   // minx,miny,maxx,maxy,amin,amax
    __shared__ int                s_nn, s_kept, s_ns;

    int b    = blockIdx.x;
    int tid  = threadIdx.x;
    int lane = tid & 31;
    int wid  = tid >> 5;
    int nc   = g_candCount[b];
    const float4* cand = g_candBox + b*PRE;
    const unsigned FULL = 0xffffffffu;

    if (tid==0) s_kept = 0;
    __syncthreads();

    for (int start=0; start<nc; start+=CHUNK){
        int kept = s_kept;
        if (kept >= POST) break;
        int n = min(CHUNK, nc-start);

        // ---- phase A: load chunk candidates
        if (tid < CHUNK && tid < n){
            float4 bx = cand[start+tid];
            cbox[tid]  = bx;
            carea[tid] = areaf(bx);
        }
        if (tid==0) s_ns = 0;
        __syncthreads();

        // ---- phase B: bbox reduce (warps 0-1) + 64x64 matrix (all threads)
        if (tid < CHUNK){
            bool ok = tid < n;
            float4 bx = ok ? cbox[tid] : make_float4(1e30f,1e30f,-1e30f,-1e30f);
            float mnx=bx.x, mny=bx.y, mxx=bx.z, mxy=bx.w;
            float amn = ok ? carea[tid] : 1e30f;
            float amx = ok ? carea[tid] : -1e30f;
            #pragma unroll
            for (int off=16; off>0; off>>=1){
                mnx=fminf(mnx,__shfl_xor_sync(FULL,mnx,off));
                mny=fminf(mny,__shfl_xor_sync(FULL,mny,off));
                mxx=fmaxf(mxx,__shfl_xor_sync(FULL,mxx,off));
                mxy=fmaxf(mxy,__shfl_xor_sync(FULL,mxy,off));
                amn=fminf(amn,__shfl_xor_sync(FULL,amn,off));
                amx=fmaxf(amx,__shfl_xor_sync(FULL,amx,off));
            }
            if (lane==0){
                s_part[wid][0]=mnx; s_part[wid][1]=mny; s_part[wid][2]=mxx;
                s_part[wid][3]=mxy; s_part[wid][4]=amn; s_part[wid][5]=amx;
            }
        }
        {
            int c = tid >> 3;           // 0..63, 8 threads per candidate
            int sub = tid & 7;
            unsigned long long m = 0ull;
            if (c < n){
                float4 A = cbox[c]; float aA = carea[c];
                for (int c2 = c+1+sub; c2 < n; c2 += 8){
                    float aB = carea[c2];
                    if (fminf(aA,aB) >= __fmul_rn(0.695f, fmaxf(aA,aB)))
                        if (iou_gt(A, aA, cbox[c2], aB)) m |= 1ull << c2;
                }
            }
            #pragma unroll
            for (int off=4; off>0; off>>=1)
                m |= __shfl_xor_sync(FULL, m, off);
            if (sub==0) s_mat[c] = m;
        }
        __syncthreads();

        // ---- phase C: filter kept list vs chunk bbox + area range
        // NOTE: trip count must be block-uniform — every lane executes every
        // iteration and the j<kept bound only predicates `pass` (R4 deadlock fix).
        {
            float bmnx=fminf(s_part[0][0],s_part[1][0]);
            float bmny=fminf(s_part[0][1],s_part[1][1]);
            float bmxx=fmaxf(s_part[0][2],s_part[1][2]);
            float bmxy=fmaxf(s_part[0][3],s_part[1][3]);
            float amn =fminf(s_part[0][4],s_part[1][4]);
            float amx =fmaxf(s_part[0][5],s_part[1][5]);
            float amnScaled = __fmul_rn(0.695f, amn);

            int iters = (kept + NMS_THREADS - 1) / NMS_THREADS;
            for (int it=0; it<iters; it++){
                int j = it*NMS_THREADS + tid;
                bool pass = false;
                if (j < kept){
                    float aB = ka[j];
                    float4 B = kb[j];
                    pass = (aB >= amnScaled) &&
                           (__fmul_rn(0.695f, aB) <= amx) &&
                           (fminf(bmxx, B.z) - fmaxf(bmnx, B.x) + 1.0f > -0.01f) &&
                           (fminf(bmxy, B.w) - fmaxf(bmny, B.y) + 1.0f > -0.01f);
                }
                unsigned bal = __ballot_sync(FULL, pass);
                int cnt = __popc(bal);
                int basep = 0;
                if (lane==0 && cnt) basep = atomicAdd(&s_ns, cnt);
                basep = __shfl_sync(FULL, basep, 0);
                if (pass) s_kidx[basep + __popc(bal & ((1u<<lane)-1u))] = (unsigned short)j;
            }
        }
        __syncthreads();

        // ---- phase D: candidates vs filtered keeps (broadcast smem loads)
        {
            int ns = s_ns;
            int c = tid & 63;
            int g = tid >> 6;           // 8 groups
            bool f = (c >= n);
            float4 A = cbox[c];
            float aA = carea[c];
            int j = g;
            #pragma unroll 1
            while (j < ns){
                #pragma unroll 4
                for (int u=0; u<4; u++){
                    if (j < ns && !f){
                        int kj = s_kidx[j];
                        float aB = ka[kj];
                        if (fminf(aA,aB) >= __fmul_rn(0.695f, fmaxf(aA,aB)))
                            f = iou_gt(A, aA, kb[kj], aB);
                    }
                    j += 8;
                }
                if (__all_sync(FULL, f)) break;
            }
            unsigned sb = __ballot_sync(FULL, f);
            if (lane==0) s_supw[wid] = sb;
        }
        __syncthreads();

        // ---- phase E: serial greedy resolve
        if (tid==0){
            unsigned lo=0u, hi=0u;
            #pragma unroll
            for (int w=0; w<16; w+=2){ lo |= s_supw[w]; hi |= s_supw[w+1]; }
            unsigned long long sup = (unsigned long long)lo |
                                     ((unsigned long long)hi << 32);
            int nn = 0;
            for (int c=0; c<n; c++){
                if (!((sup>>c)&1ull)){
                    s_new[nn++] = c;
                    sup |= s_mat[c];
                    if (kept + nn == POST) break;
                }
            }
            s_nn = nn;
            s_kept = kept + nn;
        }
        __syncthreads();

        // ---- phase F: append keeps + write outputs
        int nn = s_nn;
        if (tid < nn){
            int cc = s_new[tid];
            float4 bx = cbox[cc];
            kb[kept+tid] = bx;
            ka[kept+tid] = carea[cc];
            int row = b*POST + kept + tid;
            ((float4*)outRois)[row] = bx;
            if (writeMask) outMask[row] = 1.0f;
        }
        __syncthreads();
    }

    // ---- zero-fill tail
    int kept = s_kept;
    for (int rrow = kept + tid; rrow < POST; rrow += NMS_THREADS){
        int row = b*POST + rrow;
        ((float4*)outRois)[row] = make_float4(0.f,0.f,0.f,0.f);
        if (writeMask) outMask[row] = 0.f;
    }
}

// ---------------------------------------------------------------- launch
extern "C" void kernel_launch(void* const* d_in, const int* in_sizes, int n_in,
                              void* d_out, int out_size)
{
    (void)in_sizes; (void)n_in;
    const float4* anchors = (const float4*)d_in[0];
    const float*  cls     = (const float*)d_in[1];
    const float4* pred    = (const float4*)d_in[2];
    float* out = (float*)d_out;

    int total = BATCH*N_ANCH;
    k_decode<<<(total+255)/256, 256>>>(anchors, cls, pred);
    k_select<<<BATCH, 1024>>>();

    int writeMask = (out_size >= BATCH*POST*5) ? 1 : 0;
    k_nms<<<BATCH, NMS_THREADS>>>(out, out + BATCH*POST*4, writeMask);
}

// round 6
// speedup vs baseline: 1.6196x; 1.6196x over previous
#include <cuda_runtime.h>
#include <math.h>

#define HHv 83
#define WWv 25
#define AAv 9
#define N_ANCH (HHv*WWv*AAv)   /* 18675 */
#define BATCH 16
#define PRE 12000
#define POST 2000
#define MIN_SIZE 16.0f
#define NMS_T 0.7f
#define IMG_XF 1333.0f
#define IMG_YF 402.0f
#define FLIP_NEG_INF 0x007FFFFFu
#define CHUNK 64
#define NMS_THREADS 1024

__device__ float4   g_boxes[BATCH * N_ANCH];
__device__ unsigned g_skey [BATCH * N_ANCH];
__device__ float4   g_candBox[BATCH * PRE];
__device__ int      g_candCount[BATCH];

__device__ __forceinline__ unsigned flipf(float f){
    unsigned u = __float_as_uint(f);
    return (u & 0x80000000u) ? ~u : (u | 0x80000000u);
}

// ---------------------------------------------------------------- K1: decode
__global__ void k_decode(const float4* __restrict__ anchors,
                         const float*  __restrict__ cls,
                         const float4* __restrict__ pred)
{
    int t = blockIdx.x*blockDim.x + threadIdx.x;
    if (t >= BATCH*N_ANCH) return;
    int b = t / N_ANCH, i = t - b*N_ANCH;

    float4 a = anchors[i];
    float ah  = __fsub_rn(a.w, a.y);
    float aw  = __fsub_rn(a.z, a.x);
    float acy = __fadd_rn(a.y, __fmul_rn(0.5f, ah));
    float acx = __fadd_rn(a.x, __fmul_rn(0.5f, aw));

    float4 p = pred[t];   // dx, dy, dw, dh
    float cy = __fadd_rn(__fmul_rn(p.y, ah), acy);
    float cx = __fadd_rn(__fmul_rn(p.x, aw), acx);
    float eh = (float)exp((double)p.w);
    float ew = (float)exp((double)p.z);
    float h  = __fmul_rn(eh, ah);
    float w  = __fmul_rn(ew, aw);

    float hw = __fmul_rn(0.5f, w);
    float hh = __fmul_rn(0.5f, h);
    float x1 = fminf(fmaxf(__fsub_rn(cx, hw), 0.f), IMG_XF);
    float y1 = fminf(fmaxf(__fsub_rn(cy, hh), 0.f), IMG_YF);
    float x2 = fminf(fmaxf(__fadd_rn(cx, hw), 0.f), IMG_XF);
    float y2 = fminf(fmaxf(__fadd_rn(cy, hh), 0.f), IMG_YF);

    g_boxes[t] = make_float4(x1, y1, x2, y2);

    bool valid = (__fsub_rn(y2, y1) >= MIN_SIZE) && (__fsub_rn(x2, x1) >= MIN_SIZE);
    float s = valid ? cls[b*(2*N_ANCH) + 2*i + 1] : -INFINITY;
    g_skey[t] = flipf(s);
}

// -------------------------------------------- K2: exact top-PRE select + compact
// Parallel "find threshold bin from the top" over a histogram.
// Result: s_out[0]=bin, s_out[1]=r (1<=r<=hist[bin]); target - (count above bin) = r.
__device__ __forceinline__ void thresh_desc(const int* hist, int nb, int target,
                                            int tid, int lane, int wid,
                                            int* s_wsum, int* s_out)
{
    int half = nb >> 1;
    int h0=0, h1=0;
    if (tid < half){
        h0 = hist[nb-1-2*tid];
        h1 = hist[nb-2-2*tid];
    }
    int local = h0+h1, v = local;
    #pragma unroll
    for (int off=1; off<32; off<<=1){
        int nv = __shfl_up_sync(0xffffffffu, v, off);
        if (lane >= off) v += nv;
    }
    if (lane==31) s_wsum[wid] = v;
    __syncthreads();
    if (wid==0){
        int wv = s_wsum[lane];
        int sv = wv;
        #pragma unroll
        for (int off=1; off<32; off<<=1){
            int nv = __shfl_up_sync(0xffffffffu, sv, off);
            if (lane >= off) sv += nv;
        }
        s_wsum[lane] = sv - wv;   // exclusive prefix of warp sums
    }
    __syncthreads();
    int incl = v + s_wsum[wid];
    int excl = incl - local;
    if (tid < half){
        if (excl < target && excl + h0 >= target){
            s_out[0] = nb-1-2*tid; s_out[1] = target - excl;
        } else if (excl + h0 < target && excl + h0 + h1 >= target){
            s_out[0] = nb-2-2*tid; s_out[1] = target - excl - h0;
        }
    }
    __syncthreads();
}

__global__ void __launch_bounds__(1024) k_select()
{
    int b = blockIdx.x;
    const unsigned* skey = g_skey + b*N_ANCH;
    const int BD = 1024;
    int tid = threadIdx.x;
    int lane = tid & 31, wid = tid >> 5;

    __shared__ int      hist[2048];
    __shared__ int      s_wsum[32];
    __shared__ int      s_out[2];
    __shared__ unsigned s_T;
    __shared__ int      s_binI, s_rr, s_eqN, s_Tidx;
    __shared__ int      s_eqIdx[32];

    // ---- pass 1: bits [21,32)
    for (int j=tid;j<2048;j+=BD) hist[j]=0;
    __syncthreads();
    for (int i=tid;i<N_ANCH;i+=BD) atomicAdd(&hist[skey[i]>>21], 1);
    __syncthreads();
    thresh_desc(hist, 2048, PRE, tid, lane, wid, s_wsum, s_out);
    unsigned b0 = (unsigned)s_out[0];
    int r = s_out[1];
    __syncthreads();

    // ---- pass 2: bits [10,21)
    for (int j=tid;j<2048;j+=BD) hist[j]=0;
    __syncthreads();
    for (int i=tid;i<N_ANCH;i+=BD){
        unsigned k=skey[i];
        if ((k>>21)==b0) atomicAdd(&hist[(k>>10)&0x7FFu],1);
    }
    __syncthreads();
    thresh_desc(hist, 2048, r, tid, lane, wid, s_wsum, s_out);
    unsigned pfx = (b0<<11) | (unsigned)s_out[0];
    r = s_out[1];
    __syncthreads();

    // ---- pass 3: bits [0,10)
    for (int j=tid;j<1024;j+=BD) hist[j]=0;
    __syncthreads();
    for (int i=tid;i<N_ANCH;i+=BD){
        unsigned k=skey[i];
        if ((k>>10)==pfx) atomicAdd(&hist[k&0x3FFu],1);
    }
    __syncthreads();
    thresh_desc(hist, 1024, r, tid, lane, wid, s_wsum, s_out);
    unsigned T = (pfx<<10) | (unsigned)s_out[0];
    r = s_out[1];
    int cEq = hist[s_out[0]];
    if (tid==0) s_T = T;
    __syncthreads();
    T = s_T;

    // ---- tie-break among skey==T by ascending anchor index (rare path)
    int Tidx;
    if (r >= cEq){
        Tidx = N_ANCH;
    } else {
        for (int j=tid;j<2048;j+=BD) hist[j]=0;
        __syncthreads();
        for (int i=tid;i<N_ANCH;i+=BD)
            if (skey[i]==T) atomicAdd(&hist[i>>4],1);
        __syncthreads();
        if (tid==0){
            int cum=0, binI=0, rr=r;
            for (int bin=0;bin<2048;++bin){
                int c=hist[bin];
                if (cum+c>=r){ binI=bin; rr=r-cum; break; }
                cum+=c;
            }
            s_binI=binI; s_rr=rr; s_eqN=0;
        }
        __syncthreads();
        int binI=s_binI;
        for (int i=tid;i<N_ANCH;i+=BD)
            if (skey[i]==T && (i>>4)==binI){
                int p=atomicAdd(&s_eqN,1);
                s_eqIdx[p]=i;
            }
        __syncthreads();
        if (tid==0){
            int n=s_eqN, need=s_rr;
            for (int a2=0;a2<n;a2++)
                for (int b2=a2+1;b2<n;b2++)
                    if (s_eqIdx[b2]<s_eqIdx[a2]){
                        int tmp=s_eqIdx[a2]; s_eqIdx[a2]=s_eqIdx[b2]; s_eqIdx[b2]=tmp;
                    }
            s_Tidx = s_eqIdx[need-1];
        }
        __syncthreads();
        Tidx = s_Tidx;
    }

    // ---- compact valid+selected candidates, DESCENDING anchor index
    __shared__ int s_wcnt[32];
    const float4* boxes = g_boxes   + b*N_ANCH;
    float4*       cand  = g_candBox + b*PRE;
    int nCh = (N_ANCH + BD - 1)/BD;
    int running = 0;                     // block-uniform running total (in registers)

    for (int c=0;c<nCh;c++){
        int pos = c*BD + tid;
        int i = N_ANCH-1-pos;
        bool pred=false;
        if (i>=0){
            unsigned k = skey[i];
            bool valid = (k != FLIP_NEG_INF);
            bool sel   = (k > T) || (k==T && i<=Tidx);
            pred = valid && sel;
        }
        unsigned bal = __ballot_sync(0xffffffffu, pred);
        if (lane==0) s_wcnt[wid]=__popc(bal);
        __syncthreads();
        int base = running, tot = 0;
        #pragma unroll
        for (int w2=0;w2<32;w2++){
            int cnt = s_wcnt[w2];
            if (w2 < wid) base += cnt;
            tot += cnt;
        }
        if (pred){
            int p = base + __popc(bal & ((1u<<lane)-1u));
            cand[p] = boxes[i];
        }
        running += tot;
        __syncthreads();
    }
    if (tid==0) g_candCount[b]=running;
}

// ---------------------------------------------------------------- K3: greedy NMS
__device__ __forceinline__ bool iou_gt(const float4& A, float aA,
                                       const float4& Bx, float aB)
{
    float xx1=fmaxf(A.x,Bx.x), yy1=fmaxf(A.y,Bx.y);
    float xx2=fminf(A.z,Bx.z), yy2=fminf(A.w,Bx.w);
    float iw=__fadd_rn(__fsub_rn(xx2,xx1),1.f);
    float ih=__fadd_rn(__fsub_rn(yy2,yy1),1.f);
    float inter=__fmul_rn(fmaxf(iw,0.f), fmaxf(ih,0.f));
    float uni = __fsub_rn(__fadd_rn(aA,aB), inter);
    float ovr = __fdiv_rn(inter, uni);
    return ovr > NMS_T;
}

__device__ __forceinline__ float areaf(const float4& bx){
    return __fmul_rn(__fadd_rn(__fsub_rn(bx.z,bx.x),1.f),
                     __fadd_rn(__fsub_rn(bx.w,bx.y),1.f));
}

__global__ void __launch_bounds__(NMS_THREADS)
k_nms(float* __restrict__ outRois, float* __restrict__ outMask, int writeMask)
{
    __shared__ float4             kb[POST];
    __shared__ float              ka[POST];
    __shared__ float4             cbox[CHUNK];
    __shared__ float              carea[CHUNK];
    __shared__ unsigned long long s_mat[CHUNK];
    __shared__ unsigned           s_supw[32];
    __shared__ int                s_new[CHUNK];
    __shared__ int                s_nn, s_kept;

    int b    = blockIdx.x;
    int tid  = threadIdx.x;
    int lane = tid & 31;
    int wid  = tid >> 5;
    int nc   = g_candCount[b];
    const float4* cand = g_candBox + b*PRE;
    const unsigned FULL = 0xffffffffu;

    // prefetch chunk 0 into registers
    float4 creg = make_float4(0.f,0.f,0.f,0.f);
    if (tid < CHUNK && tid < nc) creg = cand[tid];
    if (tid==0) s_kept = 0;
    __syncthreads();

    for (int start=0; start<nc; start+=CHUNK){
        int kept = s_kept;
        if (kept >= POST) break;
        int n = min(CHUNK, nc-start);

        // ---- phase A: stage prefetched candidates into smem
        if (tid < CHUNK && tid < n){
            cbox[tid]  = creg;
            carea[tid] = areaf(creg);
        }
        __syncthreads();                       // (1)

        // prefetch next chunk (latency hidden behind B1+B2)
        {
            int nxt = start + CHUNK + tid;
            if (tid < CHUNK && nxt < nc) creg = cand[nxt];
        }

        // ---- phase B1: 64x64 forward matrix (16 threads per candidate)
        {
            int c   = tid >> 4;
            int sub = tid & 15;
            unsigned long long m = 0ull;
            if (c < n){
                float4 A = cbox[c]; float aA = carea[c];
                for (int c2 = c+1+sub; c2 < n; c2 += 16){
                    float aB = carea[c2];
                    if (fminf(aA,aB) >= __fmul_rn(0.695f, fmaxf(aA,aB)))
                        if (iou_gt(A, aA, cbox[c2], aB)) m |= 1ull << c2;
                }
            }
            #pragma unroll
            for (int off=8; off>0; off>>=1)
                m |= __shfl_xor_sync(FULL, m, off);
            if ((lane & 15)==0) s_mat[c] = m;
        }

        // ---- phase B2: candidate(c=tid&63) vs kept list, 16 groups stride 16
        {
            int c = tid & 63;
            int g = tid >> 6;                  // warp-uniform
            bool f = (c >= n);
            float4 A = cbox[c];
            float aA = carea[c];
            int j = g;
            #pragma unroll 1
            while (j < kept){
                #pragma unroll 4
                for (int u=0; u<4; u++){
                    if (j < kept && !f){
                        float aB = ka[j];
                        if (fminf(aA,aB) >= __fmul_rn(0.695f, fmaxf(aA,aB)))
                            f = iou_gt(A, aA, kb[j], aB);
                    }
                    j += 16;
                }
                if (__all_sync(FULL, f)) break;
            }
            unsigned sb = __ballot_sync(FULL, f);
            if (lane==0) s_supw[wid] = sb;
        }
        __syncthreads();                       // (2)

        // ---- phase C: warp-0 register-resident greedy resolve
        if (wid==0){
            unsigned x = s_supw[lane];         // even warps -> c[0,32), odd -> c[32,64)
            x |= __shfl_xor_sync(FULL, x, 2);
            x |= __shfl_xor_sync(FULL, x, 4);
            x |= __shfl_xor_sync(FULL, x, 8);
            x |= __shfl_xor_sync(FULL, x, 16);
            unsigned lo = __shfl_sync(FULL, x, 0);
            unsigned hi = __shfl_sync(FULL, x, 1);
            unsigned long long sup = (unsigned long long)lo |
                                     ((unsigned long long)hi << 32);
            unsigned long long m0 = s_mat[lane];
            unsigned long long m1 = s_mat[lane+32];
            unsigned long long rem = ~sup;
            if (n < 64) rem &= (1ull<<n) - 1ull;
            int nn = 0;
            while (rem != 0ull && kept+nn < POST){
                int c = __ffsll((long long)rem) - 1;
                if (lane==0) s_new[nn] = c;
                nn++;
                unsigned long long mc = __shfl_sync(FULL, (c<32)? m0 : m1, c & 31);
                rem &= ~mc;
                rem &= ~(1ull << c);
            }
            if (lane==0){ s_nn = nn; s_kept = kept + nn; }
        }
        __syncthreads();                       // (3)

        // ---- phase D: append keeps + write outputs (covered by next iter's barrier 1)
        int nn = s_nn;
        if (tid < nn){
            int cc = s_new[tid];
            float4 bx = cbox[cc];
            kb[kept+tid] = bx;
            ka[kept+tid] = carea[cc];
            int row = b*POST + kept + tid;
            ((float4*)outRois)[row] = bx;
            if (writeMask) outMask[row] = 1.0f;
        }
        __syncthreads();                       // protects kb/ka for next B2 + s_kept read
    }

    // ---- zero-fill tail
    int kept = s_kept;
    for (int rrow = kept + tid; rrow < POST; rrow += NMS_THREADS){
        int row = b*POST + rrow;
        ((float4*)outRois)[row] = make_float4(0.f,0.f,0.f,0.f);
        if (writeMask) outMask[row] = 0.f;
    }
}

// ---------------------------------------------------------------- launch
extern "C" void kernel_launch(void* const* d_in, const int* in_sizes, int n_in,
                              void* d_out, int out_size)
{
    (void)in_sizes; (void)n_in;
    const float4* anchors = (const float4*)d_in[0];
    const float*  cls     = (const float*)d_in[1];
    const float4* pred    = (const float4*)d_in[2];
    float* out = (float*)d_out;

    int total = BATCH*N_ANCH;
    k_decode<<<(total+255)/256, 256>>>(anchors, cls, pred);
    k_select<<<BATCH, 1024>>>();

    int writeMask = (out_size >= BATCH*POST*5) ? 1 : 0;
    k_nms<<<BATCH, NMS_THREADS>>>(out, out + BATCH*POST*4, writeMask);
}

// round 7
// speedup vs baseline: 3.3849x; 2.0899x over previous
#include <cuda_runtime.h>
#include <math.h>

#define HHv 83
#define WWv 25
#define AAv 9
#define N_ANCH (HHv*WWv*AAv)   /* 18675 */
#define BATCH 16
#define PRE 12000
#define POST 2000
#define MIN_SIZE 16.0f
#define NMS_T 0.7f
#define IMG_XF 1333.0f
#define IMG_YF 402.0f
#define FLIP_NEG_INF 0x007FFFFFu
#define CHUNK 64
#define NMS_THREADS 1024

#define NBINS   20
#define BINOFF  13
#define BINCAP  1024
#define SPILLCAP 2048

__device__ float4   g_boxes[BATCH * N_ANCH];
__device__ unsigned g_skey [BATCH * N_ANCH];
__device__ float4   g_candBox[BATCH * PRE];
__device__ int      g_candCount[BATCH];

__device__ __forceinline__ unsigned flipf(float f){
    unsigned u = __float_as_uint(f);
    return (u & 0x80000000u) ? ~u : (u | 0x80000000u);
}

// ---------------------------------------------------------------- K1: decode
__global__ void k_decode(const float4* __restrict__ anchors,
                         const float*  __restrict__ cls,
                         const float4* __restrict__ pred)
{
    int t = blockIdx.x*blockDim.x + threadIdx.x;
    if (t >= BATCH*N_ANCH) return;
    int b = t / N_ANCH, i = t - b*N_ANCH;

    float4 a = anchors[i];
    float ah  = __fsub_rn(a.w, a.y);
    float aw  = __fsub_rn(a.z, a.x);
    float acy = __fadd_rn(a.y, __fmul_rn(0.5f, ah));
    float acx = __fadd_rn(a.x, __fmul_rn(0.5f, aw));

    float4 p = pred[t];   // dx, dy, dw, dh
    float cy = __fadd_rn(__fmul_rn(p.y, ah), acy);
    float cx = __fadd_rn(__fmul_rn(p.x, aw), acx);
    float eh = (float)exp((double)p.w);
    float ew = (float)exp((double)p.z);
    float h  = __fmul_rn(eh, ah);
    float w  = __fmul_rn(ew, aw);

    float hw = __fmul_rn(0.5f, w);
    float hh = __fmul_rn(0.5f, h);
    float x1 = fminf(fmaxf(__fsub_rn(cx, hw), 0.f), IMG_XF);
    float y1 = fminf(fmaxf(__fsub_rn(cy, hh), 0.f), IMG_YF);
    float x2 = fminf(fmaxf(__fadd_rn(cx, hw), 0.f), IMG_XF);
    float y2 = fminf(fmaxf(__fadd_rn(cy, hh), 0.f), IMG_YF);

    g_boxes[t] = make_float4(x1, y1, x2, y2);

    bool valid = (__fsub_rn(y2, y1) >= MIN_SIZE) && (__fsub_rn(x2, x1) >= MIN_SIZE);
    float s = valid ? cls[b*(2*N_ANCH) + 2*i + 1] : -INFINITY;
    g_skey[t] = flipf(s);
}

// -------------------------------------------- K2: exact top-PRE select + compact
__device__ __forceinline__ void thresh_desc(const int* hist, int nb, int target,
                                            int tid, int lane, int wid,
                                            int* s_wsum, int* s_out)
{
    int half = nb >> 1;
    int h0=0, h1=0;
    if (tid < half){
        h0 = hist[nb-1-2*tid];
        h1 = hist[nb-2-2*tid];
    }
    int local = h0+h1, v = local;
    #pragma unroll
    for (int off=1; off<32; off<<=1){
        int nv = __shfl_up_sync(0xffffffffu, v, off);
        if (lane >= off) v += nv;
    }
    if (lane==31) s_wsum[wid] = v;
    __syncthreads();
    if (wid==0){
        int wv = s_wsum[lane];
        int sv = wv;
        #pragma unroll
        for (int off=1; off<32; off<<=1){
            int nv = __shfl_up_sync(0xffffffffu, sv, off);
            if (lane >= off) sv += nv;
        }
        s_wsum[lane] = sv - wv;
    }
    __syncthreads();
    int incl = v + s_wsum[wid];
    int excl = incl - local;
    if (tid < half){
        if (excl < target && excl + h0 >= target){
            s_out[0] = nb-1-2*tid; s_out[1] = target - excl;
        } else if (excl + h0 < target && excl + h0 + h1 >= target){
            s_out[0] = nb-2-2*tid; s_out[1] = target - excl - h0;
        }
    }
    __syncthreads();
}

__global__ void __launch_bounds__(1024) k_select()
{
    int b = blockIdx.x;
    const unsigned* skey = g_skey + b*N_ANCH;
    const int BD = 1024;
    int tid = threadIdx.x;
    int lane = tid & 31, wid = tid >> 5;

    __shared__ int      hist[2048];
    __shared__ int      s_wsum[32];
    __shared__ int      s_out[2];
    __shared__ unsigned s_T;
    __shared__ int      s_binI, s_rr, s_eqN, s_Tidx;
    __shared__ int      s_eqIdx[32];

    for (int j=tid;j<2048;j+=BD) hist[j]=0;
    __syncthreads();
    for (int i=tid;i<N_ANCH;i+=BD) atomicAdd(&hist[skey[i]>>21], 1);
    __syncthreads();
    thresh_desc(hist, 2048, PRE, tid, lane, wid, s_wsum, s_out);
    unsigned b0 = (unsigned)s_out[0];
    int r = s_out[1];
    __syncthreads();

    for (int j=tid;j<2048;j+=BD) hist[j]=0;
    __syncthreads();
    for (int i=tid;i<N_ANCH;i+=BD){
        unsigned k=skey[i];
        if ((k>>21)==b0) atomicAdd(&hist[(k>>10)&0x7FFu],1);
    }
    __syncthreads();
    thresh_desc(hist, 2048, r, tid, lane, wid, s_wsum, s_out);
    unsigned pfx = (b0<<11) | (unsigned)s_out[0];
    r = s_out[1];
    __syncthreads();

    for (int j=tid;j<1024;j+=BD) hist[j]=0;
    __syncthreads();
    for (int i=tid;i<N_ANCH;i+=BD){
        unsigned k=skey[i];
        if ((k>>10)==pfx) atomicAdd(&hist[k&0x3FFu],1);
    }
    __syncthreads();
    thresh_desc(hist, 1024, r, tid, lane, wid, s_wsum, s_out);
    unsigned T = (pfx<<10) | (unsigned)s_out[0];
    r = s_out[1];
    int cEq = hist[s_out[0]];
    if (tid==0) s_T = T;
    __syncthreads();
    T = s_T;

    int Tidx;
    if (r >= cEq){
        Tidx = N_ANCH;
    } else {
        for (int j=tid;j<2048;j+=BD) hist[j]=0;
        __syncthreads();
        for (int i=tid;i<N_ANCH;i+=BD)
            if (skey[i]==T) atomicAdd(&hist[i>>4],1);
        __syncthreads();
        if (tid==0){
            int cum=0, binI=0, rr=r;
            for (int bin=0;bin<2048;++bin){
                int c=hist[bin];
                if (cum+c>=r){ binI=bin; rr=r-cum; break; }
                cum+=c;
            }
            s_binI=binI; s_rr=rr; s_eqN=0;
        }
        __syncthreads();
        int binI=s_binI;
        for (int i=tid;i<N_ANCH;i+=BD)
            if (skey[i]==T && (i>>4)==binI){
                int p=atomicAdd(&s_eqN,1);
                s_eqIdx[p]=i;
            }
        __syncthreads();
        if (tid==0){
            int n=s_eqN, need=s_rr;
            for (int a2=0;a2<n;a2++)
                for (int b2=a2+1;b2<n;b2++)
                    if (s_eqIdx[b2]<s_eqIdx[a2]){
                        int tmp=s_eqIdx[a2]; s_eqIdx[a2]=s_eqIdx[b2]; s_eqIdx[b2]=tmp;
                    }
            s_Tidx = s_eqIdx[need-1];
        }
        __syncthreads();
        Tidx = s_Tidx;
    }

    __shared__ int s_wcnt[32];
    const float4* boxes = g_boxes   + b*N_ANCH;
    float4*       cand  = g_candBox + b*PRE;
    int nCh = (N_ANCH + BD - 1)/BD;
    int running = 0;

    for (int c=0;c<nCh;c++){
        int pos = c*BD + tid;
        int i = N_ANCH-1-pos;
        bool pred=false;
        if (i>=0){
            unsigned k = skey[i];
            bool valid = (k != FLIP_NEG_INF);
            bool sel   = (k > T) || (k==T && i<=Tidx);
            pred = valid && sel;
        }
        unsigned bal = __ballot_sync(0xffffffffu, pred);
        if (lane==0) s_wcnt[wid]=__popc(bal);
        __syncthreads();
        int base = running, tot = 0;
        #pragma unroll
        for (int w2=0;w2<32;w2++){
            int cnt = s_wcnt[w2];
            if (w2 < wid) base += cnt;
            tot += cnt;
        }
        if (pred){
            int p = base + __popc(bal & ((1u<<lane)-1u));
            cand[p] = boxes[i];
        }
        running += tot;
        __syncthreads();
    }
    if (tid==0) g_candCount[b]=running;
}

// ---------------------------------------------------------------- K3: greedy NMS
__device__ __forceinline__ float areaf(const float4& bx){
    return __fmul_rn(__fadd_rn(__fsub_rn(bx.z,bx.x),1.f),
                     __fadd_rn(__fsub_rn(bx.w,bx.y),1.f));
}

__device__ __forceinline__ int area_bin(float a){
    int bin = (int)floorf(__fmul_rn(__log2f(a), 1.7095113f)) - BINOFF;
    return min(max(bin, 0), NBINS-1);
}

// exact decision "IoU > 0.7" with guarded multiply (div only in 1e-6 band)
__device__ __forceinline__ bool iou_sup(const float4& A, float aA,
                                        const float4& Bx, float aB)
{
    float xx1=fmaxf(A.x,Bx.x), yy1=fmaxf(A.y,Bx.y);
    float xx2=fminf(A.z,Bx.z), yy2=fminf(A.w,Bx.w);
    float iw=fmaxf(__fadd_rn(__fsub_rn(xx2,xx1),1.f),0.f);
    float ih=fmaxf(__fadd_rn(__fsub_rn(yy2,yy1),1.f),0.f);
    float inter=__fmul_rn(iw,ih);
    float uni = __fsub_rn(__fadd_rn(aA,aB), inter);
    float t   = __fmul_rn(NMS_T, uni);
    if (inter > __fmul_rn(t, 1.0000010f)) return true;
    if (inter < __fmul_rn(t, 0.9999990f)) return false;
    return __fdiv_rn(inter, uni) > NMS_T;   // exact tie-band fallback (rare)
}

// dynamic smem layout (bytes)
#define SO_KB     0
#define SO_KA     32000
#define SO_BIDX   40000                       /* u16[NBINS*BINCAP] = 40960 */
#define SO_SPILL  80960                       /* u16[SPILLCAP]     = 4096  */
#define SO_CBOX   85056
#define SO_CAREA  86080
#define SO_CBIN   86336
#define SO_MAT    86592
#define SO_SUP    87104
#define SO_NEW    87168
#define SO_BCNT   87424
#define SMEM_NMS  87552

__global__ void __launch_bounds__(NMS_THREADS)
k_nms(float* __restrict__ outRois, float* __restrict__ outMask, int writeMask)
{
    extern __shared__ unsigned char sm[];
    float4*             kb      = (float4*)(sm + SO_KB);
    float*              ka      = (float*)(sm + SO_KA);
    unsigned short*     bidx    = (unsigned short*)(sm + SO_BIDX);
    unsigned short*     spill   = (unsigned short*)(sm + SO_SPILL);
    float4*             cbox    = (float4*)(sm + SO_CBOX);
    float*              carea   = (float*)(sm + SO_CAREA);
    int*                cbin    = (int*)(sm + SO_CBIN);
    unsigned long long* s_mat   = (unsigned long long*)(sm + SO_MAT);
    unsigned char*      s_sup   = sm + SO_SUP;
    int*                s_new   = (int*)(sm + SO_NEW);
    int*                s_bcnt  = (int*)(sm + SO_BCNT);

    __shared__ int s_nn, s_kept, s_spillCnt;

    int b    = blockIdx.x;
    int tid  = threadIdx.x;
    int lane = tid & 31;
    int wid  = tid >> 5;
    int nc   = g_candCount[b];
    const float4* cand = g_candBox + b*PRE;
    const unsigned FULL = 0xffffffffu;

    float4 creg = make_float4(0.f,0.f,0.f,0.f);
    if (tid < CHUNK && tid < nc) creg = cand[tid];
    if (tid==0){ s_kept = 0; s_spillCnt = 0; }
    if (tid < NBINS) s_bcnt[tid] = 0;
    __syncthreads();

    for (int start=0; start<nc; start+=CHUNK){
        int kept = s_kept;
        if (kept >= POST) break;
        int n = min(CHUNK, nc-start);

        // ---- phase A: stage prefetched candidates
        if (tid < CHUNK && tid < n){
            float a = areaf(creg);
            cbox[tid]  = creg;
            carea[tid] = a;
            cbin[tid]  = area_bin(a);
        }
        __syncthreads();                       // (1)

        // prefetch next chunk
        {
            int nxt = start + CHUNK + tid;
            if (tid < CHUNK && nxt < nc) creg = cand[nxt];
        }

        // ---- phase B1: 64x64 forward matrix (16 threads per candidate)
        {
            int c   = tid >> 4;
            int sub = tid & 15;
            unsigned long long m = 0ull;
            if (c < n){
                float4 A = cbox[c]; float aA = carea[c];
                for (int c2 = c+1+sub; c2 < n; c2 += 16){
                    float aB = carea[c2];
                    if (fminf(aA,aB) >= __fmul_rn(0.695f, fmaxf(aA,aB)))
                        if (iou_sup(A, aA, cbox[c2], aB)) m |= 1ull << c2;
                }
            }
            #pragma unroll
            for (int off=8; off>0; off>>=1)
                m |= __shfl_xor_sync(FULL, m, off);
            if ((lane & 15)==0) s_mat[c] = m;
        }

        // ---- phase B2: warp-per-candidate vs area-binned kept lists
        {
            int spillN = s_spillCnt;
            for (int cc = wid; cc < CHUNK; cc += 32){
                bool activeC = (cc < n);
                bool f = false;
                if (activeC){
                    float4 A = cbox[cc];
                    float aA = carea[cc];
                    int bA = cbin[cc];
                    int bLo = max(bA-1, 0), bHi = min(bA+1, NBINS-1);
                    for (int bb=bLo; bb<=bHi; bb++){
                        int L = s_bcnt[bb];
                        const unsigned short* lst = bidx + bb*BINCAP;
                        for (int j=lane; __any_sync(FULL, j<L); j+=32){
                            bool t=false;
                            if (j < L && !f){
                                int kj = lst[j];
                                float aB = ka[kj];
                                if (fminf(aA,aB) >= __fmul_rn(0.695f, fmaxf(aA,aB)))
                                    t = iou_sup(A, aA, kb[kj], aB);
                            }
                            f |= t;
                            if (__any_sync(FULL, f)) break;
                        }
                        if (__any_sync(FULL, f)) break;
                    }
                    if (!__any_sync(FULL, f)){
                        // spill list (normally empty)
                        for (int j=lane; __any_sync(FULL, j<spillN); j+=32){
                            bool t=false;
                            if (j < spillN && !f){
                                int kj = spill[j];
                                float aB = ka[kj];
                                if (fminf(aA,aB) >= __fmul_rn(0.695f, fmaxf(aA,aB)))
                                    t = iou_sup(A, aA, kb[kj], aB);
                            }
                            f |= t;
                            if (__any_sync(FULL, f)) break;
                        }
                    }
                }
                bool supC = __any_sync(FULL, f);
                if (lane==0) s_sup[cc] = supC ? 1 : 0;
            }
        }
        __syncthreads();                       // (2)

        // ---- phase C: warp-0 register-resident greedy resolve
        if (wid==0){
            unsigned lo = __ballot_sync(FULL, s_sup[lane] != 0);
            unsigned hi = __ballot_sync(FULL, s_sup[lane+32] != 0);
            unsigned long long sup = (unsigned long long)lo |
                                     ((unsigned long long)hi << 32);
            unsigned long long m0 = s_mat[lane];
            unsigned long long m1 = s_mat[lane+32];
            unsigned long long rem = ~sup;
            if (n < 64) rem &= (1ull<<n) - 1ull;
            int nn = 0;
            while (rem != 0ull && kept+nn < POST){
                int c = __ffsll((long long)rem) - 1;
                if (lane==0) s_new[nn] = c;
                nn++;
                unsigned long long mc = __shfl_sync(FULL, (c<32)? m0 : m1, c & 31);
                rem &= ~mc;
                rem &= ~(1ull << c);
            }
            if (lane==0){ s_nn = nn; s_kept = kept + nn; }
        }
        __syncthreads();                       // (3)

        // ---- phase D: append keeps (into bins) + write outputs
        int nn = s_nn;
        if (tid < nn){
            int cc = s_new[tid];
            float4 bx = cbox[cc];
            float a  = carea[cc];
            int ki = kept + tid;
            kb[ki] = bx;
            ka[ki] = a;
            int bn = cbin[cc];
            int slot = atomicAdd(&s_bcnt[bn], 1);
            if (slot < BINCAP){
                bidx[bn*BINCAP + slot] = (unsigned short)ki;
            } else {
                atomicSub(&s_bcnt[bn], 1);
                int sp = atomicAdd(&s_spillCnt, 1);
                spill[sp] = (unsigned short)ki;   // sp < POST <= SPILLCAP always
            }
            int row = b*POST + ki;
            ((float4*)outRois)[row] = bx;
            if (writeMask) outMask[row] = 1.0f;
        }
        __syncthreads();                       // (4)
    }

    // ---- zero-fill tail
    int kept = s_kept;
    for (int rrow = kept + tid; rrow < POST; rrow += NMS_THREADS){
        int row = b*POST + rrow;
        ((float4*)outRois)[row] = make_float4(0.f,0.f,0.f,0.f);
        if (writeMask) outMask[row] = 0.f;
    }
}

// ---------------------------------------------------------------- launch
extern "C" void kernel_launch(void* const* d_in, const int* in_sizes, int n_in,
                              void* d_out, int out_size)
{
    (void)in_sizes; (void)n_in;
    const float4* anchors = (const float4*)d_in[0];
    const float*  cls     = (const float*)d_in[1];
    const float4* pred    = (const float4*)d_in[2];
    float* out = (float*)d_out;

    cudaFuncSetAttribute(k_nms, cudaFuncAttributeMaxDynamicSharedMemorySize, SMEM_NMS);

    int total = BATCH*N_ANCH;
    k_decode<<<(total+255)/256, 256>>>(anchors, cls, pred);
    k_select<<<BATCH, 1024>>>();

    int writeMask = (out_size >= BATCH*POST*5) ? 1 : 0;
    k_nms<<<BATCH, NMS_THREADS, SMEM_NMS>>>(out, out + BATCH*POST*4, writeMask);
}